// round 8
// baseline (speedup 1.0000x reference)
#include <cuda_runtime.h>
#include <math.h>

// x: (8, 256, 32, 32) f32 ; weight: (8, 36, 64) f32 ; out: (8, 512, 32, 32) f32
#define NQ 36
#define NP 8
#define NF 33
#define NW 12              // warps (=rows) per CTA
#define NTHREADS (NW * 32)
#define CHUNKS 86          // ceil(1024 / NW)

__device__ float g_WF[NQ * NP * NF * 2];

__global__ void prep_kernel(const float* __restrict__ w) {
    int idx = blockIdx.x * blockDim.x + threadIdx.x;
    if (idx >= NQ * NP * NF) return;
    int f  = idx % NF;
    int pq = idx / NF;
    int p  = pq % NP;
    int q  = pq / NP;
    const float* wp = w + (p * NQ + q) * 64;
    float re = 0.f, im = 0.f;
    for (int m = 0; m < 64; m++) {
        int t = (f * m) & 63;
        float s, c;
        sincosf(-(float)t * 0.0981747704246810387f, &s, &c);
        re = fmaf(wp[m], c, re);
        im = fmaf(wp[m], s, im);
    }
    g_WF[idx * 2]     = re;
    g_WF[idx * 2 + 1] = im;
}

// f32x2 packed helpers
__device__ __forceinline__ unsigned long long ffma2(unsigned long long a,
                                                    unsigned long long b,
                                                    unsigned long long c) {
    unsigned long long d;
    asm("fma.rn.f32x2 %0, %1, %2, %3;" : "=l"(d) : "l"(a), "l"(b), "l"(c));
    return d;
}
__device__ __forceinline__ unsigned long long f2u(float x, float y) {
    unsigned long long v;
    asm("mov.b64 %0, {%1, %2};" : "=l"(v) : "f"(x), "f"(y));
    return v;
}
__device__ __forceinline__ float2 u2f(unsigned long long v) {
    float2 r;
    asm("mov.b64 {%0, %1}, %2;" : "=f"(r.x), "=f"(r.y) : "l"(v));
    return r;
}

// smem float offsets
#define SZ_WF    (NQ * NP * NF * 2)          // 19008
#define YT_STRIDE 522
#define SZ_YT    (NW * YT_STRIDE)            // 6264
#define SZ_Q32   (NW * 40)                   // 480
#define SZ_TW    66
#define OFF_WF   0
#define OFF_YT   (OFF_WF + SZ_WF)
#define OFF_Q32  (OFF_YT + SZ_YT)
#define OFF_TW   (OFF_Q32 + SZ_Q32)
#define SMEM_FLOATS (OFF_TW + SZ_TW)         // 25818 floats = 103272 B  (2 CTAs/SM)

__global__ void __launch_bounds__(NTHREADS, 2)
bcconv_kernel(const float* __restrict__ x, float* __restrict__ out) {
    extern __shared__ float smem[];
    float* sWF  = smem + OFF_WF;
    float* sYT  = smem + OFF_YT;
    float* sQ32 = smem + OFF_Q32;
    float* sTW  = smem + OFF_TW;

    const int tid  = threadIdx.x;
    const int wid  = tid >> 5;
    const int lane = tid & 31;
    const int bi   = blockIdx.x;
    const int b    = bi / CHUNKS;
    const int l0   = (bi - b * CHUNKS) * NW;   // first pixel of this CTA
    const int r    = l0 + wid;                 // this warp's pixel row
    const bool active = (r < 1024);

    // twiddle LUT: (cos, sin)(2*pi*k/64), k=0..32
    if (tid < 33) {
        float s, c;
        sincosf((float)tid * 0.0981747704246810387f, &s, &c);
        sTW[2 * tid]     = c;
        sTW[2 * tid + 1] = s;
    }
    // stage frequency weights
    {
        const float4* src = (const float4*)g_WF;
        float4* dst = (float4*)sWF;
        for (int i = tid; i < SZ_WF / 4; i += NTHREADS) dst[i] = src[i];
    }
    __syncthreads();

    // per-lane twiddle registers
    const float2* tw2 = (const float2*)sTW;
    const float2 wk = tw2[lane];                 // (cos, sin)(2*pi*lane/64)
    float2 stw[5];                               // DIF stage s; DIT uses stw[4-s]
#pragma unroll
    for (int s = 0; s < 5; s++) {
        int half = 16 >> s;
        stw[s] = tw2[(lane & (half - 1)) << (s + 1)];
    }
    const int pk = (32 - lane) & 31;             // conj partner
    const int rb = __brev(lane) >> 27;           // 5-bit reversal
    const int i0 = (2 * rb) & 31;                // pack shuffle sources
    const int i1 = (2 * rb + 1) & 31;
    const bool lowhalf = (rb < 16);

    float Xr[NP], Xi[NP], X32[NP];

    if (active) {
        // ---- gather cursor ----
        int G = r * 2304 + lane;
        int l = G & 1023;
        int fi = G >> 10;
        int c  = fi / 9;
        int t  = fi - c * 9;
        int t3 = t / 3;
        int dh = t3 - 1, dw = t - t3 * 3 - 1;
        const float* xc = x + ((b << 8) + c) * 1024;

        auto fetch = [&]() -> float {
            int gh = (l >> 5) + dh;
            int gw = (l & 31) + dw;
            float v = 0.f;
            if ((unsigned)gh < 32u && (unsigned)gw < 32u)
                v = __ldg(xc + (gh << 5) + gw);
            return v;
        };
        auto step = [&]() {
            l += 32;
            if (l >= 1024) {
                l -= 1024;
                if (++t == 9) { t = 0; xc += 1024; }
                t3 = t / 3;
                dh = t3 - 1; dw = t - t3 * 3 - 1;
            }
        };

        float va = fetch(); step();     // y[lane]      of block 0
        float vb = fetch(); step();     // y[lane + 32] of block 0

        unsigned long long accA[NP], accB[NP];
#pragma unroll
        for (int p = 0; p < NP; p++) { accA[p] = 0ull; accB[p] = 0ull; }
        const unsigned long long* wf8 = (const unsigned long long*)sWF;

#pragma unroll 4
        for (int q = 0; q < NQ; q++) {
            // prefetch next block
            float na = 0.f, nb = 0.f;
            if (q != NQ - 1) {
                na = fetch(); step();
                nb = fetch(); step();
            }
            // ---- pack even/odd with bit-reversed lane order ----
            // logical z[m] = y[2m] + i*y[2m+1]; lane holds z[rb]
            float a0 = __shfl_sync(0xffffffffu, va, i0);
            float b0 = __shfl_sync(0xffffffffu, vb, i0);
            float a1 = __shfl_sync(0xffffffffu, va, i1);
            float b1 = __shfl_sync(0xffffffffu, vb, i1);
            float zr = lowhalf ? a0 : b0;
            float zi = lowhalf ? a1 : b1;
            va = na; vb = nb;
            // ---- cross-lane FFT32, DIT (bitrev in / natural out) ----
#pragma unroll
            for (int s = 4; s >= 0; s--) {       // DIT stage = 4 - s (half = 16>>s)
                int half = 16 >> s;
                float ur = __shfl_xor_sync(0xffffffffu, zr, half);
                float ui = __shfl_xor_sync(0xffffffffu, zi, half);
                bool up = (lane & half) != 0;
                float bor = up ? zr : ur;
                float boi = up ? zi : ui;
                float aor = up ? ur : zr;
                float aoi = up ? ui : zi;
                // W * b with W = conj(stw[s]) = (c, -s)
                float wbr = bor * stw[s].x + boi * stw[s].y;
                float wbi = boi * stw[s].x - bor * stw[s].y;
                zr = up ? aor - wbr : aor + wbr;
                zi = up ? aoi - wbi : aoi + wbi;
            }
            // lane k now holds Z[k] (natural order)
            // X[32] = Zr[0] - Zi[0] -> stash (lane 0)
            if (lane == 0) sQ32[wid * 40 + q] = zr - zi;
            // ---- untangle to rfft64 bin X[k], k = lane ----
            float zcr =  __shfl_sync(0xffffffffu, zr, pk);
            float zci = -__shfl_sync(0xffffffffu, zi, pk);
            float Fer = 0.5f * (zr + zcr);
            float Fei = 0.5f * (zi + zci);
            float For = 0.5f * (zi - zci);
            float Foi = -0.5f * (zr - zcr);
            float xr = Fer + wk.x * For + wk.y * Foi;
            float xi = Fei + wk.x * Foi - wk.y * For;
            // ---- fused matvec accumulate ----
            unsigned long long xrr = f2u(xr, xr);
            unsigned long long xii = f2u(xi, xi);
#pragma unroll
            for (int p = 0; p < NP; p++) {
                unsigned long long wv = wf8[(q * NP + p) * NF + lane];
                accA[p] = ffma2(xrr, wv, accA[p]);   // (xr*wr, xr*wi)
                accB[p] = ffma2(xii, wv, accB[p]);   // (xi*wr, xi*wi)
            }
        }
#pragma unroll
        for (int p = 0; p < NP; p++) {
            float2 A  = u2f(accA[p]);
            float2 Bv = u2f(accB[p]);
            Xr[p] = A.x - Bv.y;
            Xi[p] = A.y + Bv.x;
        }
        __syncwarp();
        // f = 32 (pure real): warp xor-reduce over q; result in ALL lanes
        const float* q32 = sQ32 + wid * 40;
#pragma unroll
        for (int p = 0; p < NP; p++) {
            float s = q32[lane] * sWF[((lane * NP + p) * NF + 32) * 2];
            if (lane < 4)
                s += q32[32 + lane] * sWF[(((32 + lane) * NP + p) * NF + 32) * 2];
#pragma unroll
            for (int o = 16; o > 0; o >>= 1) s += __shfl_xor_sync(0xffffffffu, s, o);
            X32[p] = s;
        }

        // ---- inverse rfft64 via cross-lane FFT32 (lane = freq k) ----
        const int m = rb;
        float2* ytv = (float2*)sYT;
#pragma unroll
        for (int p = 0; p < NP; p++) {
            float xr = Xr[p], xi = Xi[p];
            float xcr =  __shfl_sync(0xffffffffu, xr, pk);
            float xci = -__shfl_sync(0xffffffffu, xi, pk);
            if (lane == 0) { xcr = X32[p]; xci = 0.f; }
            float fer = 0.5f * (xr + xcr);
            float fei = 0.5f * (xi + xci);
            float dr  = 0.5f * (xr - xcr);
            float di  = 0.5f * (xi - xci);
            float fo_r = wk.x * dr - wk.y * di;
            float fo_i = wk.x * di + wk.y * dr;
            float vr = fer - fo_i;
            float vi = -(fei + fo_r);
            // forward FFT32 across lanes (DIF, natural-in, bitrev-out)
#pragma unroll
            for (int s = 0; s < 5; s++) {
                int half = 16 >> s;
                float ur = __shfl_xor_sync(0xffffffffu, vr, half);
                float ui = __shfl_xor_sync(0xffffffffu, vi, half);
                float ddr = ur - vr, ddi = ui - vi;
                float tr = ddr * stw[s].x + ddi * stw[s].y;
                float ti = ddi * stw[s].x - ddr * stw[s].y;
                bool upper = (lane & half) != 0;
                vr = upper ? tr : vr + ur;
                vi = upper ? ti : vi + ui;
            }
            // z = conj(F)/32 ; lane holds z[m]: y[2m]=Re, y[2m+1]=-Im
            ytv[wid * (YT_STRIDE / 2) + p * 32 + m] =
                make_float2(vr * 0.03125f, -vi * 0.03125f);
        }
    }
    __syncthreads();

    // ---------- output write: out[b, ch, l0 + px] ----------
    {
        const float* yt = sYT;
        float* ob = out + (b * 512) * 1024;
        const int px  = tid % NW;
        const int ch0 = tid / NW;              // 0..31
        const int l   = l0 + px;
        if (l < 1024) {
#pragma unroll
            for (int k = 0; k < 16; k++) {
                int ch = ch0 + k * 32;
                ob[ch * 1024 + l] = yt[px * YT_STRIDE + ch];
            }
        }
    }
}

extern "C" void kernel_launch(void* const* d_in, const int* in_sizes, int n_in,
                              void* d_out, int out_size) {
    const float* x = (const float*)d_in[0];
    const float* w = (const float*)d_in[1];
    float* out = (float*)d_out;

    cudaFuncSetAttribute(bcconv_kernel,
                         cudaFuncAttributeMaxDynamicSharedMemorySize,
                         SMEM_FLOATS * (int)sizeof(float));

    prep_kernel<<<(NQ * NP * NF + 255) / 256, 256>>>(w);
    bcconv_kernel<<<8 * CHUNKS, NTHREADS, SMEM_FLOATS * sizeof(float)>>>(x, out);
}

// round 11
// speedup vs baseline: 1.0840x; 1.0840x over previous
#include <cuda_runtime.h>
#include <cuda_fp16.h>
#include <cstdint>

// x: (8, 256, 32, 32) f32 ; weight: (8, 36, 64) f32 ; out: (8, 512, 32, 32) f32
// C[R=8192, n=512] = sum_j A[R, j] * B[n, j]
//   A = im2col-flat (reference's reshape-skewed unfold), B = circulant expansion.
#define KTOT 2304
#define NCH  72          // KTOT / 32
#define THREADS 256

__device__ __half g_A[8192 * KTOT];   // 37.7 MB
__device__ __half g_B[512 * KTOT];    // 2.4 MB

// ---------------- prep: im2col to fp16 ----------------
__global__ void prep_a(const float* __restrict__ x) {
    int e = blockIdx.x * 256 + threadIdx.x;    // 8192*288 elems of 8
    int R = e / 288;
    int j0 = (e - R * 288) * 8;
    int b = R >> 10, rl = R & 1023;
    const float* xb = x + ((long)b << 18);
    __half h[8];
    int g = rl * KTOT + j0;
#pragma unroll
    for (int k = 0; k < 8; k++, g++) {
        int i = g >> 10, l = g & 1023;
        int c = i / 9, t = i - c * 9;
        int t3 = t / 3;
        int gh = (l >> 5) + t3 - 1;
        int gw = (l & 31) + (t - t3 * 3) - 1;
        float v = 0.f;
        if ((unsigned)gh < 32u && (unsigned)gw < 32u)
            v = xb[(c << 10) + (gh << 5) + gw];
        h[k] = __float2half_rn(v);
    }
    *(uint4*)(g_A + (long)R * KTOT + j0) = *(uint4*)h;
}

// ---------------- prep: circulant expansion to fp16 ----------------
__global__ void prep_b(const float* __restrict__ w) {
    int o = blockIdx.y;                        // 0..511
    int j = blockIdx.x * 256 + threadIdx.x;    // 0..2303
    int p = o >> 6, n = o & 63, q = j >> 6, m = j & 63;
    g_B[o * KTOT + j] = __float2half_rn(w[(p * 36 + q) * 64 + ((n - m + 64) & 63)]);
}

// ---------------- PTX helpers (baseline ISA only) ----------------
__device__ __forceinline__ uint32_t smem_u32(const void* p) {
    uint32_t a;
    asm("{ .reg .u64 t; cvta.to.shared.u64 t, %1; cvt.u32.u64 %0, t; }" : "=r"(a) : "l"(p));
    return a;
}
#define CP16(dst, src) \
    asm volatile("cp.async.cg.shared.global [%0], [%1], 16;" \
                 :: "r"(dst), "l"(__cvta_generic_to_global(src)) : "memory")
#define CP_COMMIT() asm volatile("cp.async.commit_group;" ::: "memory")
#define CP_WAIT1()  asm volatile("cp.async.wait_group 1;" ::: "memory")

#define LDSM4(r, a) \
    asm volatile("ldmatrix.sync.aligned.m8n8.x4.shared.b16 {%0,%1,%2,%3}, [%4];" \
        : "=r"((r)[0]), "=r"((r)[1]), "=r"((r)[2]), "=r"((r)[3]) : "r"(a))

#define MMA(d, a, b) \
    asm volatile("mma.sync.aligned.m16n8k16.row.col.f32.f16.f16.f32 " \
        "{%0,%1,%2,%3}, {%4,%5,%6,%7}, {%8,%9}, {%0,%1,%2,%3};" \
        : "+f"((d)[0]), "+f"((d)[1]), "+f"((d)[2]), "+f"((d)[3]) \
        : "r"((a)[0]), "r"((a)[1]), "r"((a)[2]), "r"((a)[3]), "r"((b)[0]), "r"((b)[1]))

// smem: 3 stages x (A 128x32 fp16 = 8K | B 128x32 fp16 = 8K) = 48 KB
#define STAGE_BYTES 16384
#define SMEM_BYTES  (3 * STAGE_BYTES)

// swizzled byte offset within an 8 KB tile: row (0..127), un = 16B unit (0..3)
__device__ __forceinline__ uint32_t swz(int row, int un) {
    return (uint32_t)(row * 64 + ((un ^ ((row >> 1) & 3)) << 4));
}

__global__ void __launch_bounds__(THREADS, 2)
gemm_kernel(float* __restrict__ out) {
    extern __shared__ char smem[];
    const uint32_t sb = smem_u32(smem);
    const int tid = threadIdx.x, wid = tid >> 5, lane = tid & 31;
    const int R0 = blockIdx.x << 7;       // pixel-row base (never crosses batch)
    const int n0 = blockIdx.y << 7;       // channel base

    // ---- cp.async source/dest (each thread: 2 A units + 2 B units per chunk) ----
    const int urow = tid >> 2, uun = tid & 3;
    const uint32_t dA = swz(urow, uun);                 // + 4096 for row+64
    const __half* srcA = g_A + (long)(R0 + urow) * KTOT + uun * 8;
    const __half* srcB = g_B + (long)(n0 + urow) * KTOT + uun * 8;

    // ---- ldmatrix per-thread geometry ----
    const int warp_m = wid >> 2, warp_n = wid & 3;
    const int rowA = warp_m * 64 + (lane & 15);
    const int khA  = lane >> 4;                          // 0/1
    const uint32_t swzA = (rowA >> 1) & 3;
    const int rowB = warp_n * 32 + ((lane >> 4) << 3) + (lane & 7);
    const int khB  = (lane >> 3) & 1;
    const uint32_t swzB = (rowB >> 1) & 3;

    float acc[4][4][4];
#pragma unroll
    for (int i = 0; i < 4; i++)
#pragma unroll
        for (int j = 0; j < 4; j++)
#pragma unroll
            for (int k = 0; k < 4; k++) acc[i][j][k] = 0.f;

    auto load_stage = [&](int c, int s) {
        uint32_t base = sb + s * STAGE_BYTES;
        const __half* pa = srcA + c * 32;
        const __half* pb = srcB + c * 32;
        CP16(base + dA, pa);
        CP16(base + dA + 4096, pa + (long)64 * KTOT);
        CP16(base + 8192 + dA, pb);
        CP16(base + 8192 + dA + 4096, pb + (long)64 * KTOT);
        CP_COMMIT();
    };

    load_stage(0, 0);
    load_stage(1, 1);

    for (int c = 0; c < NCH; c++) {
        const int s = c % 3;
        CP_WAIT1();
        __syncthreads();
        if (c + 2 < NCH) load_stage(c + 2, (c + 2) % 3);

        const uint32_t aBase = sb + s * STAGE_BYTES + rowA * 64;
        const uint32_t bBase = sb + s * STAGE_BYTES + 8192 + rowB * 64;
#pragma unroll
        for (int ks = 0; ks < 2; ks++) {
            uint32_t af[4][4], bf[4][2];
#pragma unroll
            for (int sub = 0; sub < 4; sub++)
                LDSM4(af[sub], aBase + sub * 1024 + ((((ks << 1) + khA) ^ swzA) << 4));
#pragma unroll
            for (int bt = 0; bt < 2; bt++) {
                uint32_t r[4];
                LDSM4(r, bBase + bt * 1024 + ((((ks << 1) + khB) ^ swzB) << 4));
                bf[bt * 2][0] = r[0]; bf[bt * 2][1] = r[1];
                bf[bt * 2 + 1][0] = r[2]; bf[bt * 2 + 1][1] = r[3];
            }
#pragma unroll
            for (int sub = 0; sub < 4; sub++)
#pragma unroll
                for (int nt = 0; nt < 4; nt++)
                    MMA(acc[sub][nt], af[sub], bf[nt]);
        }
        __syncthreads();
    }

    // ---- epilogue: C[R][n] -> out[b, n, pl], R = b*1024 + pl ----
    const int b = R0 >> 10;
    const int pl0 = (R0 & 1023) + warp_m * 64 + (lane >> 2);
    float* ob = out + ((long)b * 512 + n0 + warp_n * 32) * 1024;
#pragma unroll
    for (int sub = 0; sub < 4; sub++) {
        const int pl = pl0 + sub * 16;
#pragma unroll
        for (int nt = 0; nt < 4; nt++) {
            const int nn = nt * 8 + ((lane & 3) << 1);
            ob[(long)nn * 1024 + pl]           = acc[sub][nt][0];
            ob[(long)(nn + 1) * 1024 + pl]     = acc[sub][nt][1];
            ob[(long)nn * 1024 + pl + 8]       = acc[sub][nt][2];
            ob[(long)(nn + 1) * 1024 + pl + 8] = acc[sub][nt][3];
        }
    }
}

extern "C" void kernel_launch(void* const* d_in, const int* in_sizes, int n_in,
                              void* d_out, int out_size) {
    const float* x = (const float*)d_in[0];
    const float* w = (const float*)d_in[1];
    float* out = (float*)d_out;

    cudaFuncSetAttribute(gemm_kernel,
                         cudaFuncAttributeMaxDynamicSharedMemorySize, SMEM_BYTES);

    prep_a<<<8192 * 288 / 256, 256>>>(x);
    dim3 pg(KTOT / 256, 512);
    prep_b<<<pg, 256>>>(w);
    dim3 grid(64, 4);
    gemm_kernel<<<grid, THREADS, SMEM_BYTES>>>(out);
}

// round 16
// speedup vs baseline: 1.2146x; 1.1205x over previous
#include <cuda_runtime.h>
#include <cuda_fp16.h>
#include <cstdint>

// x: (8, 256, 32, 32) f32 ; weight: (8, 36, 64) f32 ; out: (8, 512, 32, 32) f32
// C[R=8192, n=512] = sum_j A[R, j] * B[n, j]
// KEY: A rows tile the unfold buffer exactly, so g_A per batch is just
// Xu[2304 features][1024 pixels] row-major (no skew) -> prep is a shifted-window copy.
#define KTOT 2304
#define NCH  72          // KTOT / 32
#define THREADS 256

__device__ __half g_A[8192 * KTOT];   // 37.7 MB  (per batch: [i=2304][l=1024])
__device__ __half g_B[512 * KTOT];    // 2.4 MB

// ---------------- prep: unfold as shifted-window copy (feature-major) ----------------
__global__ void prep_a(const float* __restrict__ x) {
    const int blk = blockIdx.x;              // b*2304 + i
    const int b = blk / KTOT;
    const int i = blk - b * KTOT;
    const int c = i / 9, t = i - c * 9;
    const int t3 = t / 3;
    const int dh = t3 - 1, dw = t - t3 * 3 - 1;
    const float* xc = x + (((b << 8) + c) << 10);

    const int l  = threadIdx.x << 2;         // 4 pixels per thread (same lh)
    const int lh = l >> 5, lw = l & 31;
    const int gh = lh + dh;
    const bool rowok = (unsigned)gh < 32u;
    __half h[4];
#pragma unroll
    for (int k = 0; k < 4; k++) {
        int gw = lw + k + dw;
        float v = 0.f;
        if (rowok && (unsigned)gw < 32u) v = __ldg(xc + (gh << 5) + gw);
        h[k] = __float2half_rn(v);
    }
    *(uint2*)(g_A + (long)blk * 1024 + l) = *(uint2*)h;
}

// ---------------- prep: circulant expansion to fp16 ----------------
__global__ void prep_b(const float* __restrict__ w) {
    int o = blockIdx.y;                        // 0..511
    int j = blockIdx.x * 256 + threadIdx.x;    // 0..2303
    int p = o >> 6, n = o & 63, q = j >> 6, m = j & 63;
    g_B[o * KTOT + j] = __float2half_rn(w[(p * 36 + q) * 64 + ((n - m + 64) & 63)]);
}

// ---------------- PTX helpers (baseline ISA only) ----------------
__device__ __forceinline__ uint32_t smem_u32(const void* p) {
    uint32_t a;
    asm("{ .reg .u64 t; cvta.to.shared.u64 t, %1; cvt.u32.u64 %0, t; }" : "=r"(a) : "l"(p));
    return a;
}
#define CP16(dst, src) \
    asm volatile("cp.async.cg.shared.global [%0], [%1], 16;" \
                 :: "r"(dst), "l"(__cvta_generic_to_global(src)) : "memory")
#define CP_COMMIT() asm volatile("cp.async.commit_group;" ::: "memory")
#define CP_WAIT1()  asm volatile("cp.async.wait_group 1;" ::: "memory")

#define LDSM4(r, a) \
    asm volatile("ldmatrix.sync.aligned.m8n8.x4.shared.b16 {%0,%1,%2,%3}, [%4];" \
        : "=r"((r)[0]), "=r"((r)[1]), "=r"((r)[2]), "=r"((r)[3]) : "r"(a))

#define MMA(d, a, b) \
    asm volatile("mma.sync.aligned.m16n8k16.row.col.f32.f16.f16.f32 " \
        "{%0,%1,%2,%3}, {%4,%5,%6,%7}, {%8,%9}, {%0,%1,%2,%3};" \
        : "+f"((d)[0]), "+f"((d)[1]), "+f"((d)[2]), "+f"((d)[3]) \
        : "r"((a)[0]), "r"((a)[1]), "r"((a)[2]), "r"((a)[3]), "r"((b)[0]), "r"((b)[1]))

// smem: 3 stages x (A 128x32 fp16 = 8K | B 128x32 fp16 = 8K) = 48 KB
#define STAGE_BYTES 16384
#define SMEM_BYTES  (3 * STAGE_BYTES)

// swizzled byte offset within an 8 KB tile: row (0..127), un = 16B unit (0..3)
__device__ __forceinline__ uint32_t swz(int row, int un) {
    return (uint32_t)(row * 64 + ((un ^ ((row >> 1) & 3)) << 4));
}

__global__ void __launch_bounds__(THREADS, 2)
gemm_kernel(float* __restrict__ out) {
    extern __shared__ char smem[];
    const uint32_t sb = smem_u32(smem);
    const int tid = threadIdx.x, wid = tid >> 5, lane = tid & 31;
    const int R0 = blockIdx.x << 7;       // pixel-row base (never crosses batch)
    const int n0 = blockIdx.y << 7;       // channel base

    // ---- cp.async source/dest (each thread: 2 A units + 2 B units per chunk) ----
    const int urow = tid >> 2, uun = tid & 3;
    const uint32_t dA = swz(urow, uun);                 // + 4096 for row+64
    const __half* srcA = g_A + (long)(R0 + urow) * KTOT + uun * 8;
    const __half* srcB = g_B + (long)(n0 + urow) * KTOT + uun * 8;

    // ---- ldmatrix per-thread geometry ----
    const int warp_m = wid >> 2, warp_n = wid & 3;
    const int rowA = warp_m * 64 + (lane & 15);
    const int khA  = lane >> 4;                          // 0/1
    const uint32_t swzA = (rowA >> 1) & 3;
    const int rowB = warp_n * 32 + ((lane >> 4) << 3) + (lane & 7);
    const int khB  = (lane >> 3) & 1;
    const uint32_t swzB = (rowB >> 1) & 3;

    float acc[4][4][4];
#pragma unroll
    for (int i = 0; i < 4; i++)
#pragma unroll
        for (int j = 0; j < 4; j++)
#pragma unroll
            for (int k = 0; k < 4; k++) acc[i][j][k] = 0.f;

    auto load_stage = [&](int c, int s) {
        uint32_t base = sb + s * STAGE_BYTES;
        const __half* pa = srcA + c * 32;
        const __half* pb = srcB + c * 32;
        CP16(base + dA, pa);
        CP16(base + dA + 4096, pa + (long)64 * KTOT);
        CP16(base + 8192 + dA, pb);
        CP16(base + 8192 + dA + 4096, pb + (long)64 * KTOT);
        CP_COMMIT();
    };

    load_stage(0, 0);
    load_stage(1, 1);

    for (int c = 0; c < NCH; c++) {
        const int s = c % 3;
        CP_WAIT1();
        __syncthreads();
        if (c + 2 < NCH) load_stage(c + 2, (c + 2) % 3);

        const uint32_t aBase = sb + s * STAGE_BYTES + rowA * 64;
        const uint32_t bBase = sb + s * STAGE_BYTES + 8192 + rowB * 64;
#pragma unroll
        for (int ks = 0; ks < 2; ks++) {
            uint32_t af[4][4], bf[4][2];
#pragma unroll
            for (int sub = 0; sub < 4; sub++)
                LDSM4(af[sub], aBase + sub * 1024 + ((((ks << 1) + khA) ^ swzA) << 4));
#pragma unroll
            for (int bt = 0; bt < 2; bt++) {
                uint32_t r[4];
                LDSM4(r, bBase + bt * 1024 + ((((ks << 1) + khB) ^ swzB) << 4));
                bf[bt * 2][0] = r[0]; bf[bt * 2][1] = r[1];
                bf[bt * 2 + 1][0] = r[2]; bf[bt * 2 + 1][1] = r[3];
            }
#pragma unroll
            for (int sub = 0; sub < 4; sub++)
#pragma unroll
                for (int nt = 0; nt < 4; nt++)
                    MMA(acc[sub][nt], af[sub], bf[nt]);
        }
        __syncthreads();
    }

    // ---- epilogue: C[R][n] -> out[b, n, pl], R = b*1024 + pl ----
    const int b = R0 >> 10;
    const int pl0 = (R0 & 1023) + warp_m * 64 + (lane >> 2);
    float* ob = out + ((long)b * 512 + n0 + warp_n * 32) * 1024;
#pragma unroll
    for (int sub = 0; sub < 4; sub++) {
        const int pl = pl0 + sub * 16;
#pragma unroll
        for (int nt = 0; nt < 4; nt++) {
            const int nn = nt * 8 + ((lane & 3) << 1);
            ob[(long)nn * 1024 + pl]           = acc[sub][nt][0];
            ob[(long)(nn + 1) * 1024 + pl]     = acc[sub][nt][1];
            ob[(long)nn * 1024 + pl + 8]       = acc[sub][nt][2];
            ob[(long)(nn + 1) * 1024 + pl + 8] = acc[sub][nt][3];
        }
    }
}

extern "C" void kernel_launch(void* const* d_in, const int* in_sizes, int n_in,
                              void* d_out, int out_size) {
    const float* x = (const float*)d_in[0];
    const float* w = (const float*)d_in[1];
    float* out = (float*)d_out;

    cudaFuncSetAttribute(gemm_kernel,
                         cudaFuncAttributeMaxDynamicSharedMemorySize, SMEM_BYTES);

    dim3 pg(KTOT / 256, 512);
    prep_b<<<pg, 256>>>(w);
    prep_a<<<8 * KTOT, 256>>>(x);
    dim3 grid(64, 4);
    gemm_kernel<<<grid, THREADS, SMEM_BYTES>>>(out);
}